// round 9
// baseline (speedup 1.0000x reference)
#include <cuda_runtime.h>
#include <cuda_bf16.h>
#include <cstdint>

// ICPMatcher: exact NN via capacity-binned 32^3 grid + warp-cooperative rings.
//
// 3 launches total (launch overhead dominated the R8 profile):
//   k_zero: clear per-cell counters + overflow counter
//   k_fill: bin targets into g_pts[cell][CAP] via atomicAdd (no prefix scan);
//           overflow (statistically ~impossible, CAP = mean+5.5 sigma) goes to
//           a global list
//   k_nn:   one warp per source; ring r's cells lane-strided, per-lane packed
//           (monotone(d')|idx) u64 min, warp shfl-min per ring, prune
//           ((r-1)h)^2 > bestD2 + margin; then tail-scan the overflow list.
//
// Exactness: scanned set is a superset containing the true NN; distance math
// (fma chain) and u64-min tie-break identical to all passing rounds; u64-min
// is order-independent so atomic slot order cannot change the result.

typedef unsigned long long ull;

#define N_MAX   16384
#define G       32
#define NCELLS  (G * G * G)          // 32768
#define CAP     96
#define OVCAP   4096
#define BBOX    6.0f
#define CELLH   0.375f
#define INVH    2.6666667f

static __device__ int    g_cnt[NCELLS];
static __device__ float4 g_pts[NCELLS * CAP];   // (x,y,z, bitcast(origIdx))
static __device__ int    g_ovCnt;
static __device__ float4 g_ov[OVCAP];

static __device__ __forceinline__ unsigned int map_f32(float f) {
    unsigned int b = __float_as_uint(f);
    return (b & 0x80000000u) ? ~b : (b | 0x80000000u);
}
static __device__ __forceinline__ float unmap_f32(unsigned int m) {
    return __uint_as_float((m & 0x80000000u) ? (m ^ 0x80000000u) : ~m);
}
static __device__ __forceinline__ int clampi(int v, int lo, int hi) {
    return v < lo ? lo : (v > hi ? hi : v);
}
static __device__ __forceinline__ void cellOf(float x, float y, float z,
                                              int& cx, int& cy, int& cz) {
    cx = clampi((int)floorf((x + BBOX) * INVH), 0, G - 1);
    cy = clampi((int)floorf((y + BBOX) * INVH), 0, G - 1);
    cz = clampi((int)floorf((z + BBOX) * INVH), 0, G - 1);
}

// ---- binning ---------------------------------------------------------------

__global__ void k_zero() {
    int i = blockIdx.x * blockDim.x + threadIdx.x;
    if (i < NCELLS / 4) ((int4*)g_cnt)[i] = make_int4(0, 0, 0, 0);
    if (i == 0) g_ovCnt = 0;
}

__global__ void k_fill(const float* __restrict__ tgt, int n2) {
    int i = blockIdx.x * blockDim.x + threadIdx.x;
    if (i < n2) {
        float x = tgt[3 * i], y = tgt[3 * i + 1], z = tgt[3 * i + 2];
        int cx, cy, cz;
        cellOf(x, y, z, cx, cy, cz);
        const int c = (cz * G + cy) * G + cx;
        int pos = atomicAdd(&g_cnt[c], 1);
        if (pos < CAP) {
            g_pts[c * CAP + pos] = make_float4(x, y, z, __int_as_float(i));
        } else {
            int op = atomicAdd(&g_ovCnt, 1);
            if (op < OVCAP)
                g_ov[op] = make_float4(x, y, z, __int_as_float(i));
        }
    }
}

// ---- warp-cooperative NN search --------------------------------------------

__global__ __launch_bounds__(256) void k_nn(const float* __restrict__ src,
                                            float* __restrict__ out,
                                            int n1, int out_size) {
    const int warp = (blockIdx.x * blockDim.x + threadIdx.x) >> 5;
    const int lane = threadIdx.x & 31;
    if (warp >= n1) return;
    const int i = warp;

    const float x = src[3 * i], y = src[3 * i + 1], z = src[3 * i + 2];
    const float m2x = -2.f * x, m2y = -2.f * y, m2z = -2.f * z;
    const float s2 = fmaf(x, x, fmaf(y, y, z * z));

    int cx, cy, cz;
    cellOf(x, y, z, cx, cy, cz);

    ull best = 0xFFFFFFFFFFFFFFFFull;
    float bestD2 = __int_as_float(0x7f800000);

    // r=1 scans the full 3x3x3 cube (rings 0+1); r>=2 shell only.
    for (int r = 1; r <= G; r++) {
        if (r > 1) {
            float lb = (float)(r - 1) * CELLH;
            if (lb * lb > bestD2 + 1e-3f) break;
        }
        const int side = 2 * r + 1;
        const int area = side * side;
        const int ncub = side * area;

        ull lbest = best;
        for (int t = lane; t < ncub; t += 32) {
            const int dz = t / area - r;
            const int rm = t % area;
            const int dy = rm / side - r;
            const int dx = rm % side - r;
            if (r > 1) {
                const int ch = max(abs(dx), max(abs(dy), abs(dz)));
                if (ch < r) continue;            // interior already scanned
            }
            const int xx = cx + dx, yy = cy + dy, zz = cz + dz;
            if (xx < 0 || xx >= G || yy < 0 || yy >= G || zz < 0 || zz >= G)
                continue;
            const int c = (zz * G + yy) * G + xx;
            int cnt = __ldg(&g_cnt[c]);
            if (cnt > CAP) cnt = CAP;            // overflow handled separately
            const float4* cell = &g_pts[c * CAP];
            for (int p = 0; p < cnt; p++) {
                const float4 T = __ldg(&cell[p]);
                float t2 = fmaf(T.x, T.x, fmaf(T.y, T.y, T.z * T.z));
                float d  = fmaf(m2x, T.x, fmaf(m2y, T.y, fmaf(m2z, T.z, t2)));
                ull pk = ((ull)map_f32(d) << 32) |
                         (unsigned int)__float_as_int(T.w);
                if (pk < lbest) lbest = pk;
            }
        }

#pragma unroll
        for (int off = 16; off > 0; off >>= 1) {
            ull o = __shfl_xor_sync(0xFFFFFFFFu, lbest, off);
            if (o < lbest) lbest = o;
        }
        best = lbest;
        if (best != 0xFFFFFFFFFFFFFFFFull)
            bestD2 = unmap_f32((unsigned int)(best >> 32)) + s2;
    }

    // Overflow tail-scan (empty in practice; guarantees exactness).
    {
        int ov = g_ovCnt;
        if (ov > OVCAP) ov = OVCAP;
        ull lbest = best;
        for (int p = lane; p < ov; p += 32) {
            const float4 T = g_ov[p];
            float t2 = fmaf(T.x, T.x, fmaf(T.y, T.y, T.z * T.z));
            float d  = fmaf(m2x, T.x, fmaf(m2y, T.y, fmaf(m2z, T.z, t2)));
            ull pk = ((ull)map_f32(d) << 32) |
                     (unsigned int)__float_as_int(T.w);
            if (pk < lbest) lbest = pk;
        }
        if (ov > 0) {
#pragma unroll
            for (int off = 16; off > 0; off >>= 1) {
                ull o = __shfl_xor_sync(0xFFFFFFFFu, lbest, off);
                if (o < lbest) lbest = o;
            }
        }
        best = lbest;
    }

    if (lane == 0) {
        const float dist = unmap_f32((unsigned int)(best >> 32)) + s2;
        const unsigned int idx = (unsigned int)(best & 0xFFFFFFFFu);
        if (i < out_size) out[i] = dist;
        if (n1 + i < out_size) out[n1 + i] = (float)idx;
    }
}

// ---- launch ----------------------------------------------------------------

extern "C" void kernel_launch(void* const* d_in, const int* in_sizes, int n_in,
                              void* d_out, int out_size) {
    const float* src = (const float*)d_in[0];
    const float* tgt = (const float*)d_in[1];
    const int n1 = in_sizes[0] / 3;
    const int n2 = in_sizes[1] / 3;
    float* out = (float*)d_out;

    k_zero<<<(NCELLS / 4 + 255) / 256, 256>>>();
    k_fill<<<(n2 + 255) / 256, 256>>>(tgt, n2);

    const int warps_per_cta = 256 / 32;
    k_nn<<<(n1 + warps_per_cta - 1) / warps_per_cta, 256>>>(src, out, n1, out_size);
}